// round 5
// baseline (speedup 1.0000x reference)
#include <cuda_runtime.h>
#include <cuda_bf16.h>
#include <cstdint>

#define BB   8
#define LL   50
#define BL   400
#define MM   32
#define NHOP 2
#define DD   64
#define HH   2
#define HDD  32
#define RR   20
#define NBLK 2

// ---------------- scratch ----------------------------------------------------
__device__ float g_item [BL*DD];
__device__ float g_osum [BL*DD];
__device__ float g_V    [BL*RR*DD];
__device__ float g_x    [BL*DD];
__device__ float g_Q    [BL*DD];
__device__ float g_ctx  [BL*DD];

__device__ __forceinline__ float lrelu(float x) { return x > 0.f ? x : 0.01f * x; }

// ---------------- K1: V[bl,r,j] = sum_i item[bl,i] * R_r[i,j] ----------------
// grid = 320 : (r 0..19) x (chunk-of-25 0..15). 256 threads.
// R column j held in 64 registers; items broadcast from smem.
__global__ __launch_bounds__(256) void k_vcomp3(
    const float* __restrict__ rel, const float* __restrict__ E,
    const int* __restrict__ seq, int hop)
{
    __shared__ __align__(16) float IT[25*DD];
    int u = blockIdx.x;
    int r = u >> 4, c = u & 15;
    int t = threadIdx.x;
    int j = t & 63, gg = t >> 6;

    // R_r column j -> registers (coalesced: warp spans 32 consecutive j)
    float Rj[64];
    const float* Rr = rel + (long)r*4096 + j;
    #pragma unroll
    for (int i = 0; i < 64; i++) Rj[i] = Rr[i*64];

    int base = c * 25;
    for (int idx = t; idx < 25*DD; idx += 256) {
        int bl = base + (idx >> 6), d = idx & 63;
        IT[idx] = hop ? g_item[bl*DD + d] : E[(long)seq[bl]*DD + d];
    }
    __syncthreads();

    for (int l = gg; l < 25; l += 4) {
        const float4* it4 = (const float4*)(IT + l*DD);
        float a0 = 0.f, a1 = 0.f, a2 = 0.f, a3 = 0.f;
        #pragma unroll
        for (int k2 = 0; k2 < 4; k2++) {
            float4 x0 = it4[k2], x1 = it4[k2+4], x2 = it4[k2+8], x3 = it4[k2+12];
            a0 += x0.x*Rj[4*k2   ] + x0.y*Rj[4*k2+1 ] + x0.z*Rj[4*k2+2 ] + x0.w*Rj[4*k2+3 ];
            a1 += x1.x*Rj[4*k2+16] + x1.y*Rj[4*k2+17] + x1.z*Rj[4*k2+18] + x1.w*Rj[4*k2+19];
            a2 += x2.x*Rj[4*k2+32] + x2.y*Rj[4*k2+33] + x2.z*Rj[4*k2+34] + x2.w*Rj[4*k2+35];
            a3 += x3.x*Rj[4*k2+48] + x3.y*Rj[4*k2+49] + x3.z*Rj[4*k2+50] + x3.w*Rj[4*k2+51];
        }
        g_V[((long)(base + l)*RR + r)*DD + j] = (a0 + a1) + (a2 + a3);
    }
}

// ---------------- K2: per-(b,l) hop update -----------------------------------
__global__ __launch_bounds__(128) void k_hop(
    const float* __restrict__ E, const float* __restrict__ Wt,
    const int* __restrict__ mh, const int* __restrict__ mr, const int* __restrict__ mt,
    const int* __restrict__ seq, int hop, int last)
{
    __shared__ float sc[MM], pr[MM], u[DD], part[128], item_s[DD];
    int bl = blockIdx.x, t = threadIdx.x;
    if (t < DD)
        item_s[t] = hop ? g_item[bl*DD + t] : E[(long)seq[bl]*DD + t];

    int m = t >> 2, q4 = t & 3;
    int midx = (bl*NHOP + hop) * MM + m;
    int hid = mh[midx], rid = mr[midx];
    const float4* Vv = (const float4*)(g_V + ((long)bl*RR + rid) * DD) + q4*4;
    const float4* Hh = (const float4*)(E + (long)hid * DD) + q4*4;
    float acc = 0.f;
    #pragma unroll
    for (int i = 0; i < 4; i++) {
        float4 a = Vv[i], b = Hh[i];
        acc += a.x*b.x + a.y*b.y + a.z*b.z + a.w*b.w;
    }
    acc += __shfl_down_sync(0xffffffffu, acc, 2, 4);
    acc += __shfl_down_sync(0xffffffffu, acc, 1, 4);
    if (q4 == 0) sc[m] = acc;
    __syncthreads();

    if (t < 32) {
        float v = sc[t];
        float mx = v;
        #pragma unroll
        for (int o = 16; o; o >>= 1) mx = fmaxf(mx, __shfl_xor_sync(0xffffffffu, mx, o));
        float e = __expf(v - mx);
        float s = e;
        #pragma unroll
        for (int o = 16; o; o >>= 1) s += __shfl_xor_sync(0xffffffffu, s, o);
        pr[t] = e / s;
    }
    __syncthreads();

    int d = t & 63, half = t >> 6;
    float od = 0.f;
    #pragma unroll 4
    for (int m2 = half*16; m2 < half*16 + 16; m2++) {
        int te = mt[(bl*NHOP + hop) * MM + m2];
        od += pr[m2] * E[(long)te * DD + d];
    }
    part[t] = od;
    __syncthreads();
    if (t < DD) {
        float o = part[t] + part[t + 64];
        if (hop == 0) g_osum[bl*DD + t] = o;
        else          g_osum[bl*DD + t] += o;
        u[t] = o + item_s[t];
    }
    __syncthreads();

    if (!last) {
        const float4* wr = (const float4*)(Wt + d*DD) + half*8;
        const float4* uu = (const float4*)u + half*8;
        float a = 0.f;
        #pragma unroll
        for (int kk = 0; kk < 8; kk++) {
            float4 w = wr[kk], x = uu[kk];
            a += w.x*x.x + w.y*x.y + w.z*x.z + w.w*x.w;
        }
        part[t] = a;
        __syncthreads();
        if (t < DD) {
            float s = part[t] + part[t + 64];
            g_item[bl*DD + t] = lrelu(s);
        }
    }
}

// ---------------- K3: sequential interest scan (per batch b) -----------------
__global__ __launch_bounds__(128) void k_scan(
    const float* __restrict__ W1, const float* __restrict__ W2,
    const float* __restrict__ uemb, const int* __restrict__ user,
    const float* __restrict__ pemb, const float* __restrict__ E,
    const int* __restrict__ seq)
{
    __shared__ float S[LL*DD];
    __shared__ float AB[128];
    __shared__ float T[128];
    int b = blockIdx.x, t = threadIdx.x;
    int i = t & 63, path = t >> 6;

    const float* W = path ? W2 : W1;
    const float4* wr = (const float4*)(W + i*DD);
    float4 wv[16];
    #pragma unroll
    for (int kk = 0; kk < 16; kk++) wv[kk] = wr[kk];

    for (int idx = t; idx < LL*DD; idx += 128) {
        int l = idx >> 6, d = idx & 63;
        S[idx] = E[(long)seq[b*LL + l]*DD + d] + g_osum[b*LL*DD + idx];
    }

    float c = uemb[(long)user[b] * DD + i];
    __syncthreads();

    for (int st = 0; st < LL; st++) {
        float sv = S[st*DD + i];
        AB[path*64 + i] = path ? (sv * c) : (sv + c);
        __syncthreads();
        const float4* in = (const float4*)(AB + path*64);
        float a0 = 0.f, a1 = 0.f, a2 = 0.f, a3 = 0.f;
        #pragma unroll
        for (int kk = 0; kk < 16; kk += 4) {
            float4 x0 = in[kk],   x1 = in[kk+1], x2 = in[kk+2], x3 = in[kk+3];
            a0 += wv[kk  ].x*x0.x + wv[kk  ].y*x0.y + wv[kk  ].z*x0.z + wv[kk  ].w*x0.w;
            a1 += wv[kk+1].x*x1.x + wv[kk+1].y*x1.y + wv[kk+1].z*x1.z + wv[kk+1].w*x1.w;
            a2 += wv[kk+2].x*x2.x + wv[kk+2].y*x2.y + wv[kk+2].z*x2.z + wv[kk+2].w*x2.w;
            a3 += wv[kk+3].x*x3.x + wv[kk+3].y*x3.y + wv[kk+3].z*x3.z + wv[kk+3].w*x3.w;
        }
        float r = lrelu((a0 + a1) + (a2 + a3));
        T[path*64 + i] = r;
        __syncthreads();
        float out = T[i] + T[64 + i];
        c = out;
        if (path == 0)
            g_x[(b*LL + st)*DD + i] = out * 8.0f + pemb[st*DD + i];
    }
}

// ---------------- K5: fused LN + qkv + causal attention, block = (b,h) -------
// smem layout (floats): xs@0[3200], qh@3200[1800], kh@5000[1800], vh@6800[1800],
//                       Qs@8600[3200], ps aliases Qs region (Qs dead by then).
__global__ __launch_bounds__(256) void k_attn2(
    const float* __restrict__ lnas, const float* __restrict__ lnab,
    const float* __restrict__ ipw,  const float* __restrict__ ipb, int bb)
{
    __shared__ __align__(16) float sm[11800];
    float* xs = sm;            // [50][64]
    float* qh = sm + 3200;     // [50][36]
    float* kh = sm + 5000;     // [50][36]
    float* vh = sm + 6800;     // [50][36]
    float* Qs = sm + 8600;     // [50][64]
    float* ps = sm + 8600;     // [8][52] (aliases Qs after q-proj)

    int blk = blockIdx.x, b = blk >> 1, h = blk & 1, t = threadIdx.x;
    int w = t >> 5, lane = t & 31;

    // step 1: load x rows
    for (int idx = t; idx < LL*DD; idx += 256)
        xs[idx] = g_x[b*LL*DD + idx];
    __syncthreads();

    // step 2: LN per row -> Qs (+ g_Q from h==0)
    for (int l = w; l < LL; l += 8) {
        float d0 = xs[l*DD + lane], d1 = xs[l*DD + lane + 32];
        float s = d0 + d1;
        #pragma unroll
        for (int o = 16; o; o >>= 1) s += __shfl_xor_sync(0xffffffffu, s, o);
        float mean = s * (1.f/64.f);
        float e0 = d0 - mean, e1 = d1 - mean;
        float vs = e0*e0 + e1*e1;
        #pragma unroll
        for (int o = 16; o; o >>= 1) vs += __shfl_xor_sync(0xffffffffu, vs, o);
        float inv = rsqrtf(vs * (1.f/64.f) + 1e-8f);
        float q0 = e0 * inv * lnas[bb*DD + lane]      + lnab[bb*DD + lane];
        float q1 = e1 * inv * lnas[bb*DD + lane + 32] + lnab[bb*DD + lane + 32];
        Qs[l*DD + lane] = q0;
        Qs[l*DD + lane + 32] = q1;
        if (h == 0) {
            g_Q[(b*LL + l)*DD + lane] = q0;
            g_Q[(b*LL + l)*DD + lane + 32] = q1;
        }
    }
    __syncthreads();

    // step 3: q projection (head slice): 50 rows x 32 outputs = 1600 units
    for (int u2 = t; u2 < LL*HDD; u2 += 256) {
        int l = u2 >> 5, oo = u2 & 31;
        int orow = bb*3*DD + h*HDD + oo;
        const float4* w4 = (const float4*)(ipw + (long)orow*DD);
        const float4* s4 = (const float4*)(Qs + l*DD);
        float acc = 0.f;
        #pragma unroll
        for (int kk = 0; kk < 16; kk++) {
            float4 ww = w4[kk], xx = s4[kk];
            acc += ww.x*xx.x + ww.y*xx.y + ww.z*xx.z + ww.w*xx.w;
        }
        qh[l*36 + oo] = acc + ipb[orow];
    }
    __syncthreads();   // Qs dead; ps region usable after this

    // step 4: k,v projections from xs: 50 rows x 64 outputs = 3200 units
    for (int u2 = t; u2 < LL*DD; u2 += 256) {
        int l = u2 >> 6, z = u2 & 63;
        int which = z >> 5, oo = z & 31;   // 0=k, 1=v
        int orow = bb*3*DD + DD + which*DD + h*HDD + oo;
        const float4* w4 = (const float4*)(ipw + (long)orow*DD);
        const float4* s4 = (const float4*)(xs + l*DD);
        float acc = 0.f;
        #pragma unroll
        for (int kk = 0; kk < 16; kk++) {
            float4 ww = w4[kk], xx = s4[kk];
            acc += ww.x*xx.x + ww.y*xx.y + ww.z*xx.z + ww.w*xx.w;
        }
        float r = acc + ipb[orow];
        if (which == 0) kh[l*36 + oo] = r;
        else            vh[l*36 + oo] = r;
    }
    __syncthreads();

    // step 5: causal attention
    const float scl = 0.17677669529663687f;   // 1/sqrt(32)
    for (int qi = w; qi < LL; qi += 8) {
        float4 qreg[8];
        const float4* qa = (const float4*)(qh + qi*36);
        #pragma unroll
        for (int kk = 0; kk < 8; kk++) qreg[kk] = qa[kk];

        int k0 = lane, k1 = lane + 32;
        float s0 = -3.0e38f, s1 = -3.0e38f;
        if (k0 <= qi) {
            const float4* ka = (const float4*)(kh + k0*36);
            float a = 0.f;
            #pragma unroll
            for (int kk = 0; kk < 8; kk++) {
                float4 kv = ka[kk];
                a += qreg[kk].x*kv.x + qreg[kk].y*kv.y + qreg[kk].z*kv.z + qreg[kk].w*kv.w;
            }
            s0 = a * scl;
        }
        if (k1 <= qi) {
            const float4* ka = (const float4*)(kh + k1*36);
            float a = 0.f;
            #pragma unroll
            for (int kk = 0; kk < 8; kk++) {
                float4 kv = ka[kk];
                a += qreg[kk].x*kv.x + qreg[kk].y*kv.y + qreg[kk].z*kv.z + qreg[kk].w*kv.w;
            }
            s1 = a * scl;
        }
        float mx = fmaxf(s0, s1);
        #pragma unroll
        for (int o = 16; o; o >>= 1) mx = fmaxf(mx, __shfl_xor_sync(0xffffffffu, mx, o));
        float e0 = (k0 <= qi) ? __expf(s0 - mx) : 0.f;
        float e1 = (k1 <= qi) ? __expf(s1 - mx) : 0.f;
        float smv = e0 + e1;
        #pragma unroll
        for (int o = 16; o; o >>= 1) smv += __shfl_xor_sync(0xffffffffu, smv, o);
        float inv = 1.f / smv;
        ps[w*52 + k0] = e0 * inv;
        if (k1 < LL) ps[w*52 + k1] = e1 * inv;
        __syncwarp();
        float acc = 0.f;
        for (int kj = 0; kj <= qi; kj++)
            acc += ps[w*52 + kj] * vh[kj*36 + lane];
        g_ctx[(b*LL + qi)*DD + h*HDD + lane] = acc;
        __syncwarp();
    }
}

// ---------------- K6: out-proj + residual + LN + FFN (+ final LN/logits) -----
__global__ __launch_bounds__(128) void k_mlp(
    const float* __restrict__ opw, const float* __restrict__ opb,
    const float* __restrict__ fs,  const float* __restrict__ fb,
    const float* __restrict__ c1w, const float* __restrict__ c1b,
    const float* __restrict__ c2w, const float* __restrict__ c2b, int bb,
    int last, const float* __restrict__ E,
    const float* __restrict__ lls, const float* __restrict__ llb,
    const int* __restrict__ pos, const int* __restrict__ neg,
    float* __restrict__ out)
{
    __shared__ float cs[DD], xr[DD], x2[DD], hdn[DD], part[128];
    __shared__ float mv[2];
    int bl = blockIdx.x, t = threadIdx.x;
    int i = t & 63, half = t >> 6;
    if (t < DD) cs[t] = g_ctx[bl*DD + t];
    __syncthreads();

    {
        const float4* wr = (const float4*)(opw + ((long)bb*DD + i)*DD) + half*8;
        const float4* uu = (const float4*)cs + half*8;
        float a = 0.f;
        #pragma unroll
        for (int kk = 0; kk < 8; kk++) {
            float4 w = wr[kk], x = uu[kk];
            a += w.x*x.x + w.y*x.y + w.z*x.z + w.w*x.w;
        }
        part[t] = a;
    }
    __syncthreads();
    if (t < DD)
        xr[t] = part[t] + part[t+64] + opb[bb*DD + t] + g_Q[bl*DD + t];
    __syncthreads();

    if (t < 32) {
        float s = xr[t] + xr[t+32];
        #pragma unroll
        for (int o = 16; o; o >>= 1) s += __shfl_xor_sync(0xffffffffu, s, o);
        float mean = s * (1.f/64.f);
        float d0 = xr[t]-mean, d1 = xr[t+32]-mean;
        float vs = d0*d0 + d1*d1;
        #pragma unroll
        for (int o = 16; o; o >>= 1) vs += __shfl_xor_sync(0xffffffffu, vs, o);
        if (t == 0) { mv[0] = mean; mv[1] = rsqrtf(vs*(1.f/64.f) + 1e-8f); }
    }
    __syncthreads();
    if (t < DD)
        x2[t] = (xr[t] - mv[0]) * mv[1] * fs[bb*DD + t] + fb[bb*DD + t];
    __syncthreads();

    {
        const float4* wr = (const float4*)(c1w + ((long)bb*DD + i)*DD) + half*8;
        const float4* uu = (const float4*)x2 + half*8;
        float a = 0.f;
        #pragma unroll
        for (int kk = 0; kk < 8; kk++) {
            float4 w = wr[kk], x = uu[kk];
            a += w.x*x.x + w.y*x.y + w.z*x.z + w.w*x.w;
        }
        part[t] = a;
    }
    __syncthreads();
    if (t < DD) {
        float v = part[t] + part[t+64] + c1b[bb*DD + t];
        hdn[t] = v > 0.f ? v : 0.f;
    }
    __syncthreads();

    {
        const float4* wr = (const float4*)(c2w + ((long)bb*DD + i)*DD) + half*8;
        const float4* uu = (const float4*)hdn + half*8;
        float a = 0.f;
        #pragma unroll
        for (int kk = 0; kk < 8; kk++) {
            float4 w = wr[kk], x = uu[kk];
            a += w.x*x.x + w.y*x.y + w.z*x.z + w.w*x.w;
        }
        part[t] = a;
    }
    __syncthreads();

    if (!last) {
        if (t < DD)
            g_x[bl*DD + t] = x2[t] + part[t] + part[t+64] + c2b[bb*DD + t];
        return;
    }

    // fused final LN + logits
    if (t < DD)
        xr[t] = x2[t] + part[t] + part[t+64] + c2b[bb*DD + t];
    __syncthreads();
    if (t < 32) {
        float s = xr[t] + xr[t+32];
        #pragma unroll
        for (int o = 16; o; o >>= 1) s += __shfl_xor_sync(0xffffffffu, s, o);
        float mean = s * (1.f/64.f);
        float d0 = xr[t]-mean, d1 = xr[t+32]-mean;
        float vs = d0*d0 + d1*d1;
        #pragma unroll
        for (int o = 16; o; o >>= 1) vs += __shfl_xor_sync(0xffffffffu, vs, o);
        if (t == 0) { mv[0] = mean; mv[1] = rsqrtf(vs*(1.f/64.f) + 1e-8f); }
    }
    __syncthreads();
    if (t < DD) {
        float lf = (xr[t] - mv[0]) * mv[1] * lls[t] + llb[t];
        part[t]      = lf * E[(long)pos[bl]*DD + t];
        part[t + 64] = lf * E[(long)neg[bl]*DD + t];
    }
    __syncthreads();
    if (t < 32) {
        float s = part[t] + part[t+32];
        #pragma unroll
        for (int o = 16; o; o >>= 1) s += __shfl_xor_sync(0xffffffffu, s, o);
        if (t == 0) out[bl] = s;
    } else if (t < 64) {
        int tn = t - 32;
        float s = part[64 + tn] + part[96 + tn];
        #pragma unroll
        for (int o = 16; o; o >>= 1) s += __shfl_xor_sync(0xffffffffu, s, o);
        if (tn == 0) out[BL + bl] = s;
    }
}

// ---------------- launch ------------------------------------------------------
extern "C" void kernel_launch(void* const* d_in, const int* in_sizes, int n_in,
                              void* d_out, int out_size)
{
    const float* uemb = (const float*)d_in[0];
    const float* E    = (const float*)d_in[1];
    const float* rel  = (const float*)d_in[2];
    const float* Wt   = (const float*)d_in[3];
    const float* W1   = (const float*)d_in[4];
    const float* W2   = (const float*)d_in[5];
    const float* pemb = (const float*)d_in[6];
    const float* lnas = (const float*)d_in[7];
    const float* lnab = (const float*)d_in[8];
    const float* ipw  = (const float*)d_in[9];
    const float* ipb  = (const float*)d_in[10];
    const float* opw  = (const float*)d_in[11];
    const float* opb  = (const float*)d_in[12];
    const float* fs   = (const float*)d_in[13];
    const float* fb   = (const float*)d_in[14];
    const float* c1w  = (const float*)d_in[15];
    const float* c1b  = (const float*)d_in[16];
    const float* c2w  = (const float*)d_in[17];
    const float* c2b  = (const float*)d_in[18];
    const float* lls  = (const float*)d_in[19];
    const float* llb  = (const float*)d_in[20];
    const int*   user = (const int*)d_in[21];
    const int*   seq  = (const int*)d_in[22];
    const int*   pos  = (const int*)d_in[23];
    const int*   neg  = (const int*)d_in[24];
    const int*   mh   = (const int*)d_in[25];
    const int*   mr   = (const int*)d_in[26];
    const int*   mt   = (const int*)d_in[27];
    float* out = (float*)d_out;

    for (int hop = 0; hop < NHOP; hop++) {
        k_vcomp3<<<320, 256>>>(rel, E, seq, hop);
        k_hop<<<BL, 128>>>(E, Wt, mh, mr, mt, seq, hop, hop == NHOP - 1);
    }
    k_scan<<<BB, 128>>>(W1, W2, uemb, user, pemb, E, seq);
    for (int bb = 0; bb < NBLK; bb++) {
        k_attn2<<<BB*HH, 256>>>(lnas, lnab, ipw, ipb, bb);
        k_mlp<<<BL, 128>>>(opw, opb, fs, fb, c1w, c1b, c2w, c2b, bb,
                           bb == NBLK - 1, E, lls, llb, pos, neg, out);
    }
}

// round 8
// speedup vs baseline: 1.0833x; 1.0833x over previous
#include <cuda_runtime.h>
#include <cuda_bf16.h>
#include <cstdint>

#define BB   8
#define LL   50
#define BL   400
#define MM   32
#define NHOP 2
#define DD   64
#define HH   2
#define HDD  32
#define RR   20
#define NBLK 2

// ---------------- scratch ----------------------------------------------------
__device__ float g_item [BL*DD];
__device__ float g_osum [BL*DD];
__device__ float g_V    [BL*RR*DD];
__device__ float g_x    [BL*DD];
__device__ float g_Q    [BL*DD];
__device__ float g_q    [BL*DD];
__device__ float g_k    [BL*DD];
__device__ float g_v    [BL*DD];
__device__ float g_ctx  [BL*DD];

__device__ __forceinline__ float lrelu(float x) { return x > 0.f ? x : 0.01f * x; }

// ---------------- V[bl,r,j] = sum_i item[bl,i] * R_r[i,j] --------------------
// grid = 320 : (r 0..19) x (chunk-of-25 0..15). 256 threads.
__global__ __launch_bounds__(256) void kv_rip(
    const float* __restrict__ rel, const float* __restrict__ E,
    const int* __restrict__ seq, int hop)
{
    __shared__ __align__(16) float IT[25*DD];
    const int u = blockIdx.x;
    const int r = u >> 4, c = u & 15;
    const int t = threadIdx.x;
    const int j = t & 63, gg = t >> 6;

    float Rj[64];
    const float* Rr = rel + (long)r*4096 + j;
    #pragma unroll
    for (int i = 0; i < 64; i++) Rj[i] = Rr[i*64];

    const int base = c * 25;
    for (int idx = t; idx < 25*DD; idx += 256) {
        int bl = base + (idx >> 6), d = idx & 63;
        IT[idx] = hop ? g_item[bl*DD + d] : E[(long)seq[bl]*DD + d];
    }
    __syncthreads();

    for (int l = gg; l < 25; l += 4) {
        const float4* it4 = (const float4*)(IT + l*DD);
        float a0 = 0.f, a1 = 0.f, a2 = 0.f, a3 = 0.f;
        #pragma unroll
        for (int k2 = 0; k2 < 4; k2++) {
            float4 x0 = it4[k2], x1 = it4[k2+4], x2 = it4[k2+8], x3 = it4[k2+12];
            a0 += x0.x*Rj[4*k2   ] + x0.y*Rj[4*k2+1 ] + x0.z*Rj[4*k2+2 ] + x0.w*Rj[4*k2+3 ];
            a1 += x1.x*Rj[4*k2+16] + x1.y*Rj[4*k2+17] + x1.z*Rj[4*k2+18] + x1.w*Rj[4*k2+19];
            a2 += x2.x*Rj[4*k2+32] + x2.y*Rj[4*k2+33] + x2.z*Rj[4*k2+34] + x2.w*Rj[4*k2+35];
            a3 += x3.x*Rj[4*k2+48] + x3.y*Rj[4*k2+49] + x3.z*Rj[4*k2+50] + x3.w*Rj[4*k2+51];
        }
        g_V[((long)(base + l)*RR + r)*DD + j] = (a0 + a1) + (a2 + a3);
    }
}

// ---------------- per-(b,l) hop update, t-rows prefetched --------------------
__global__ __launch_bounds__(128) void kh_rip(
    const float* __restrict__ E, const float* __restrict__ Wt,
    const int* __restrict__ mh, const int* __restrict__ mr, const int* __restrict__ mt,
    const int* __restrict__ seq, int hop, int last)
{
    __shared__ float sc[MM], pr[MM], u[DD], part[128], item_s[DD];
    const int bl = blockIdx.x, t = threadIdx.x;
    const int d = t & 63, half = t >> 6;
    const int mbase = (bl*NHOP + hop) * MM;

    if (t < DD)
        item_s[t] = hop ? g_item[bl*DD + t] : E[(long)seq[bl]*DD + t];

    // ---- issue score loads ----
    const int m = t >> 2, q4 = t & 3;
    const int hid = mh[mbase + m], rid = mr[mbase + m];
    const float4* Vv = (const float4*)(g_V + ((long)bl*RR + rid) * DD) + q4*4;
    const float4* Hh = (const float4*)(E + (long)hid * DD) + q4*4;
    float4 va[4], ha[4];
    #pragma unroll
    for (int i = 0; i < 4; i++) { va[i] = Vv[i]; ha[i] = Hh[i]; }

    // ---- prefetch t-rows (consumed only after softmax) ----
    float treg[16];
    const int* mtb = mt + mbase + half*16;
    #pragma unroll
    for (int m2 = 0; m2 < 16; m2++)
        treg[m2] = E[(long)mtb[m2]*DD + d];

    // ---- score reduction ----
    float acc = 0.f;
    #pragma unroll
    for (int i = 0; i < 4; i++)
        acc += va[i].x*ha[i].x + va[i].y*ha[i].y + va[i].z*ha[i].z + va[i].w*ha[i].w;
    acc += __shfl_down_sync(0xffffffffu, acc, 2, 4);
    acc += __shfl_down_sync(0xffffffffu, acc, 1, 4);
    if (q4 == 0) sc[m] = acc;
    __syncthreads();

    // ---- softmax over 32 (warp 0) ----
    if (t < 32) {
        float v = sc[t];
        float mx = v;
        #pragma unroll
        for (int o = 16; o; o >>= 1) mx = fmaxf(mx, __shfl_xor_sync(0xffffffffu, mx, o));
        float e = __expf(v - mx);
        float s = e;
        #pragma unroll
        for (int o = 16; o; o >>= 1) s += __shfl_xor_sync(0xffffffffu, s, o);
        pr[t] = e / s;
    }
    __syncthreads();

    // ---- o[d] from prefetched registers ----
    float od = 0.f;
    #pragma unroll
    for (int m2 = 0; m2 < 16; m2++)
        od += pr[half*16 + m2] * treg[m2];
    part[t] = od;
    __syncthreads();
    if (t < DD) {
        float o = part[t] + part[t + 64];
        if (hop == 0) g_osum[bl*DD + t] = o;
        else          g_osum[bl*DD + t] += o;
        u[t] = o + item_s[t];
    }
    __syncthreads();

    if (!last) {
        const float4* wr = (const float4*)(Wt + d*DD) + half*8;
        const float4* uu = (const float4*)u + half*8;
        float a = 0.f;
        #pragma unroll
        for (int kk = 0; kk < 8; kk++) {
            float4 w = wr[kk], x = uu[kk];
            a += w.x*x.x + w.y*x.y + w.z*x.z + w.w*x.w;
        }
        part[t] = a;
        __syncthreads();
        if (t < DD)
            g_item[bl*DD + t] = lrelu(part[t] + part[t + 64]);
    }
}

// ---------------- sequential interest scan (per batch b) ---------------------
__global__ __launch_bounds__(128) void ks_rip(
    const float* __restrict__ W1, const float* __restrict__ W2,
    const float* __restrict__ uemb, const int* __restrict__ user,
    const float* __restrict__ pemb, const float* __restrict__ E,
    const int* __restrict__ seq)
{
    __shared__ float S[LL*DD];
    __shared__ float AB[128];
    __shared__ float T[128];
    const int b = blockIdx.x, t = threadIdx.x;
    const int i = t & 63, path = t >> 6;

    const float* W = path ? W2 : W1;
    const float4* wr = (const float4*)(W + i*DD);
    float4 wv[16];
    #pragma unroll
    for (int kk = 0; kk < 16; kk++) wv[kk] = wr[kk];

    for (int idx = t; idx < LL*DD; idx += 128) {
        int l = idx >> 6, d = idx & 63;
        S[idx] = E[(long)seq[b*LL + l]*DD + d] + g_osum[b*LL*DD + idx];
    }

    float c = uemb[(long)user[b] * DD + i];
    __syncthreads();

    for (int st = 0; st < LL; st++) {
        float sv = S[st*DD + i];
        AB[path*64 + i] = path ? (sv * c) : (sv + c);
        __syncthreads();
        const float4* in = (const float4*)(AB + path*64);
        float a0 = 0.f, a1 = 0.f, a2 = 0.f, a3 = 0.f;
        #pragma unroll
        for (int kk = 0; kk < 16; kk += 4) {
            float4 x0 = in[kk],   x1 = in[kk+1], x2 = in[kk+2], x3 = in[kk+3];
            a0 += wv[kk  ].x*x0.x + wv[kk  ].y*x0.y + wv[kk  ].z*x0.z + wv[kk  ].w*x0.w;
            a1 += wv[kk+1].x*x1.x + wv[kk+1].y*x1.y + wv[kk+1].z*x1.z + wv[kk+1].w*x1.w;
            a2 += wv[kk+2].x*x2.x + wv[kk+2].y*x2.y + wv[kk+2].z*x2.z + wv[kk+2].w*x2.w;
            a3 += wv[kk+3].x*x3.x + wv[kk+3].y*x3.y + wv[kk+3].z*x3.z + wv[kk+3].w*x3.w;
        }
        float r = lrelu((a0 + a1) + (a2 + a3));
        T[path*64 + i] = r;
        __syncthreads();
        float out = T[i] + T[64 + i];
        c = out;
        if (path == 0)
            g_x[(b*LL + st)*DD + i] = out * 8.0f + pemb[st*DD + i];
    }
}

// ---------------- per-row LN -> Q, then q/k/v projections --------------------
__global__ __launch_bounds__(128) void kq_rip(
    const float* __restrict__ lns, const float* __restrict__ lnb,
    const float* __restrict__ ipw, const float* __restrict__ ipb, int bb)
{
    __shared__ float xs[DD], Qs[DD];
    __shared__ float mv[2];
    const int bl = blockIdx.x, t = threadIdx.x;
    if (t < DD) xs[t] = g_x[bl*DD + t];
    __syncthreads();
    if (t < 32) {
        float s = xs[t] + xs[t + 32];
        #pragma unroll
        for (int o = 16; o; o >>= 1) s += __shfl_xor_sync(0xffffffffu, s, o);
        float mean = s * (1.f/64.f);
        float d0 = xs[t] - mean, d1 = xs[t+32] - mean;
        float vs = d0*d0 + d1*d1;
        #pragma unroll
        for (int o = 16; o; o >>= 1) vs += __shfl_xor_sync(0xffffffffu, vs, o);
        if (t == 0) { mv[0] = mean; mv[1] = rsqrtf(vs * (1.f/64.f) + 1e-8f); }
    }
    __syncthreads();
    if (t < DD) {
        float q = (xs[t] - mv[0]) * mv[1] * lns[bb*DD + t] + lnb[bb*DD + t];
        Qs[t] = q;
        g_Q[bl*DD + t] = q;
    }
    __syncthreads();

    for (int o = t; o < 3*DD; o += 128) {
        const float* src = (o < DD) ? Qs : xs;
        const float4* w4 = (const float4*)(ipw + ((long)bb*3*DD + o) * DD);
        const float4* s4 = (const float4*)src;
        float acc = 0.f;
        #pragma unroll
        for (int kk = 0; kk < 16; kk++) {
            float4 w = w4[kk], x = s4[kk];
            acc += w.x*x.x + w.y*x.y + w.z*x.z + w.w*x.w;
        }
        acc += ipb[bb*3*DD + o];
        if      (o < DD)   g_q[bl*DD + o      ] = acc;
        else if (o < 2*DD) g_k[bl*DD + o - 64 ] = acc;
        else               g_v[bl*DD + o - 128] = acc;
    }
}

// ---------------- causal attention, block = (b,h) ----------------------------
__global__ __launch_bounds__(256) void ka_rip()
{
    __shared__ float qh[LL*36], kh[LL*36], vh[LL*36];
    __shared__ float ps[8][52];
    const int blk = blockIdx.x, b = blk >> 1, h = blk & 1, t = threadIdx.x;

    for (int idx = t; idx < LL*HDD; idx += 256) {
        int l = idx >> 5, d = idx & 31;
        int src = (b*LL + l)*DD + h*HDD + d;
        qh[l*36 + d] = g_q[src];
        kh[l*36 + d] = g_k[src];
        vh[l*36 + d] = g_v[src];
    }
    __syncthreads();

    const int w = t >> 5, lane = t & 31;
    const float scl = 0.17677669529663687f;
    for (int qi = w; qi < LL; qi += 8) {
        float4 qreg[8];
        const float4* qa = (const float4*)(qh + qi*36);
        #pragma unroll
        for (int kk = 0; kk < 8; kk++) qreg[kk] = qa[kk];

        int k0 = lane, k1 = lane + 32;
        float s0 = -3.0e38f, s1 = -3.0e38f;
        if (k0 <= qi) {
            const float4* ka = (const float4*)(kh + k0*36);
            float a = 0.f;
            #pragma unroll
            for (int kk = 0; kk < 8; kk++) {
                float4 kv = ka[kk];
                a += qreg[kk].x*kv.x + qreg[kk].y*kv.y + qreg[kk].z*kv.z + qreg[kk].w*kv.w;
            }
            s0 = a * scl;
        }
        if (k1 <= qi) {
            const float4* ka = (const float4*)(kh + k1*36);
            float a = 0.f;
            #pragma unroll
            for (int kk = 0; kk < 8; kk++) {
                float4 kv = ka[kk];
                a += qreg[kk].x*kv.x + qreg[kk].y*kv.y + qreg[kk].z*kv.z + qreg[kk].w*kv.w;
            }
            s1 = a * scl;
        }
        float mx = fmaxf(s0, s1);
        #pragma unroll
        for (int o = 16; o; o >>= 1) mx = fmaxf(mx, __shfl_xor_sync(0xffffffffu, mx, o));
        float e0 = (k0 <= qi) ? __expf(s0 - mx) : 0.f;
        float e1 = (k1 <= qi) ? __expf(s1 - mx) : 0.f;
        float sm = e0 + e1;
        #pragma unroll
        for (int o = 16; o; o >>= 1) sm += __shfl_xor_sync(0xffffffffu, sm, o);
        float inv = 1.f / sm;
        ps[w][k0] = e0 * inv;
        if (k1 < LL) ps[w][k1] = e1 * inv;
        __syncwarp();
        float acc = 0.f;
        for (int kj = 0; kj <= qi; kj++)
            acc += ps[w][kj] * vh[kj*36 + lane];
        g_ctx[(b*LL + qi)*DD + h*HDD + lane] = acc;
        __syncwarp();
    }
}

// ---------------- out-proj + residual + LN + FFN (+ final LN/logits) ---------
__global__ __launch_bounds__(128) void km_rip(
    const float* __restrict__ opw, const float* __restrict__ opb,
    const float* __restrict__ fs,  const float* __restrict__ fb,
    const float* __restrict__ c1w, const float* __restrict__ c1b,
    const float* __restrict__ c2w, const float* __restrict__ c2b, int bb,
    int last, const float* __restrict__ E,
    const float* __restrict__ lls, const float* __restrict__ llb,
    const int* __restrict__ pos, const int* __restrict__ neg,
    float* __restrict__ out)
{
    __shared__ float cs[DD], xr[DD], x2[DD], hdn[DD], part[128];
    __shared__ float mv[2];
    const int bl = blockIdx.x, t = threadIdx.x;
    const int i = t & 63, half = t >> 6;
    if (t < DD) cs[t] = g_ctx[bl*DD + t];
    __syncthreads();

    {
        const float4* wr = (const float4*)(opw + ((long)bb*DD + i)*DD) + half*8;
        const float4* uu = (const float4*)cs + half*8;
        float a = 0.f;
        #pragma unroll
        for (int kk = 0; kk < 8; kk++) {
            float4 w = wr[kk], x = uu[kk];
            a += w.x*x.x + w.y*x.y + w.z*x.z + w.w*x.w;
        }
        part[t] = a;
    }
    __syncthreads();
    if (t < DD)
        xr[t] = part[t] + part[t+64] + opb[bb*DD + t] + g_Q[bl*DD + t];
    __syncthreads();

    if (t < 32) {
        float s = xr[t] + xr[t+32];
        #pragma unroll
        for (int o = 16; o; o >>= 1) s += __shfl_xor_sync(0xffffffffu, s, o);
        float mean = s * (1.f/64.f);
        float d0 = xr[t]-mean, d1 = xr[t+32]-mean;
        float vs = d0*d0 + d1*d1;
        #pragma unroll
        for (int o = 16; o; o >>= 1) vs += __shfl_xor_sync(0xffffffffu, vs, o);
        if (t == 0) { mv[0] = mean; mv[1] = rsqrtf(vs*(1.f/64.f) + 1e-8f); }
    }
    __syncthreads();
    if (t < DD)
        x2[t] = (xr[t] - mv[0]) * mv[1] * fs[bb*DD + t] + fb[bb*DD + t];
    __syncthreads();

    {
        const float4* wr = (const float4*)(c1w + ((long)bb*DD + i)*DD) + half*8;
        const float4* uu = (const float4*)x2 + half*8;
        float a = 0.f;
        #pragma unroll
        for (int kk = 0; kk < 8; kk++) {
            float4 w = wr[kk], x = uu[kk];
            a += w.x*x.x + w.y*x.y + w.z*x.z + w.w*x.w;
        }
        part[t] = a;
    }
    __syncthreads();
    if (t < DD) {
        float v = part[t] + part[t+64] + c1b[bb*DD + t];
        hdn[t] = v > 0.f ? v : 0.f;
    }
    __syncthreads();

    {
        const float4* wr = (const float4*)(c2w + ((long)bb*DD + i)*DD) + half*8;
        const float4* uu = (const float4*)hdn + half*8;
        float a = 0.f;
        #pragma unroll
        for (int kk = 0; kk < 8; kk++) {
            float4 w = wr[kk], x = uu[kk];
            a += w.x*x.x + w.y*x.y + w.z*x.z + w.w*x.w;
        }
        part[t] = a;
    }
    __syncthreads();

    if (!last) {
        if (t < DD)
            g_x[bl*DD + t] = x2[t] + part[t] + part[t+64] + c2b[bb*DD + t];
        return;
    }

    // fused final LN + logits
    if (t < DD)
        xr[t] = x2[t] + part[t] + part[t+64] + c2b[bb*DD + t];
    __syncthreads();
    if (t < 32) {
        float s = xr[t] + xr[t+32];
        #pragma unroll
        for (int o = 16; o; o >>= 1) s += __shfl_xor_sync(0xffffffffu, s, o);
        float mean = s * (1.f/64.f);
        float d0 = xr[t]-mean, d1 = xr[t+32]-mean;
        float vs = d0*d0 + d1*d1;
        #pragma unroll
        for (int o = 16; o; o >>= 1) vs += __shfl_xor_sync(0xffffffffu, vs, o);
        if (t == 0) { mv[0] = mean; mv[1] = rsqrtf(vs*(1.f/64.f) + 1e-8f); }
    }
    __syncthreads();
    if (t < DD) {
        float lf = (xr[t] - mv[0]) * mv[1] * lls[t] + llb[t];
        part[t]      = lf * E[(long)pos[bl]*DD + t];
        part[t + 64] = lf * E[(long)neg[bl]*DD + t];
    }
    __syncthreads();
    if (t < 32) {
        float s = part[t] + part[t+32];
        #pragma unroll
        for (int o = 16; o; o >>= 1) s += __shfl_xor_sync(0xffffffffu, s, o);
        if (t == 0) out[bl] = s;
    } else if (t < 64) {
        int tn = t - 32;
        float s = part[64 + tn] + part[96 + tn];
        #pragma unroll
        for (int o = 16; o; o >>= 1) s += __shfl_xor_sync(0xffffffffu, s, o);
        if (tn == 0) out[BL + bl] = s;
    }
}

// ---------------- launch ------------------------------------------------------
extern "C" void kernel_launch(void* const* d_in, const int* in_sizes, int n_in,
                              void* d_out, int out_size)
{
    const float* uemb = (const float*)d_in[0];
    const float* E    = (const float*)d_in[1];
    const float* rel  = (const float*)d_in[2];
    const float* Wt   = (const float*)d_in[3];
    const float* W1   = (const float*)d_in[4];
    const float* W2   = (const float*)d_in[5];
    const float* pemb = (const float*)d_in[6];
    const float* lnas = (const float*)d_in[7];
    const float* lnab = (const float*)d_in[8];
    const float* ipw  = (const float*)d_in[9];
    const float* ipb  = (const float*)d_in[10];
    const float* opw  = (const float*)d_in[11];
    const float* opb  = (const float*)d_in[12];
    const float* fs   = (const float*)d_in[13];
    const float* fb   = (const float*)d_in[14];
    const float* c1w  = (const float*)d_in[15];
    const float* c1b  = (const float*)d_in[16];
    const float* c2w  = (const float*)d_in[17];
    const float* c2b  = (const float*)d_in[18];
    const float* lls  = (const float*)d_in[19];
    const float* llb  = (const float*)d_in[20];
    const int*   user = (const int*)d_in[21];
    const int*   seq  = (const int*)d_in[22];
    const int*   pos  = (const int*)d_in[23];
    const int*   neg  = (const int*)d_in[24];
    const int*   mh   = (const int*)d_in[25];
    const int*   mr   = (const int*)d_in[26];
    const int*   mt   = (const int*)d_in[27];
    float* out = (float*)d_out;

    for (int hop = 0; hop < NHOP; hop++) {
        kv_rip<<<320, 256>>>(rel, E, seq, hop);
        kh_rip<<<BL, 128>>>(E, Wt, mh, mr, mt, seq, hop, hop == NHOP - 1);
    }
    ks_rip<<<BB, 128>>>(W1, W2, uemb, user, pemb, E, seq);
    for (int bb = 0; bb < NBLK; bb++) {
        kq_rip<<<BL, 128>>>(lnas, lnab, ipw, ipb, bb);
        ka_rip<<<BB*HH, 256>>>();
        km_rip<<<BL, 128>>>(opw, opb, fs, fb, c1w, c1b, c2w, c2b, bb,
                            bb == NBLK - 1, E, lls, llb, pos, neg, out);
    }
}

// round 9
// speedup vs baseline: 1.1555x; 1.0666x over previous
#include <cuda_runtime.h>
#include <cuda_bf16.h>
#include <cstdint>

#define BB   8
#define LL   50
#define BL   400
#define MM   32
#define NHOP 2
#define DD   64
#define HH   2
#define HDD  32
#define RR   20
#define NBLK 2

// ---------------- scratch ----------------------------------------------------
__device__ float g_item [BL*DD];
__device__ float g_osum [BL*DD];
__device__ float g_V    [BL*RR*DD];
__device__ float g_x    [BL*DD];
__device__ float g_Q    [BL*DD];
__device__ float g_q    [BL*DD];
__device__ float g_k    [BL*DD];
__device__ float g_v    [BL*DD];
__device__ float g_ctx  [BL*DD];

__device__ __forceinline__ float lrelu(float x) { return x > 0.f ? x : 0.01f * x; }

// ---------------- V[bl,r,j] = sum_i item[bl,i] * R_r[i,j] --------------------
__global__ __launch_bounds__(256) void kv_rip(
    const float* __restrict__ rel, const float* __restrict__ E,
    const int* __restrict__ seq, int hop)
{
    __shared__ __align__(16) float IT[25*DD];
    const int u = blockIdx.x;
    const int r = u >> 4, c = u & 15;
    const int t = threadIdx.x;
    const int j = t & 63, gg = t >> 6;

    float Rj[64];
    const float* Rr = rel + (long)r*4096 + j;
    #pragma unroll
    for (int i = 0; i < 64; i++) Rj[i] = Rr[i*64];

    const int base = c * 25;
    for (int idx = t; idx < 25*DD; idx += 256) {
        int bl = base + (idx >> 6), d = idx & 63;
        IT[idx] = hop ? g_item[bl*DD + d] : E[(long)seq[bl]*DD + d];
    }
    __syncthreads();

    for (int l = gg; l < 25; l += 4) {
        const float4* it4 = (const float4*)(IT + l*DD);
        float a0 = 0.f, a1 = 0.f, a2 = 0.f, a3 = 0.f;
        #pragma unroll
        for (int k2 = 0; k2 < 4; k2++) {
            float4 x0 = it4[k2], x1 = it4[k2+4], x2 = it4[k2+8], x3 = it4[k2+12];
            a0 += x0.x*Rj[4*k2   ] + x0.y*Rj[4*k2+1 ] + x0.z*Rj[4*k2+2 ] + x0.w*Rj[4*k2+3 ];
            a1 += x1.x*Rj[4*k2+16] + x1.y*Rj[4*k2+17] + x1.z*Rj[4*k2+18] + x1.w*Rj[4*k2+19];
            a2 += x2.x*Rj[4*k2+32] + x2.y*Rj[4*k2+33] + x2.z*Rj[4*k2+34] + x2.w*Rj[4*k2+35];
            a3 += x3.x*Rj[4*k2+48] + x3.y*Rj[4*k2+49] + x3.z*Rj[4*k2+50] + x3.w*Rj[4*k2+51];
        }
        g_V[((long)(base + l)*RR + r)*DD + j] = (a0 + a1) + (a2 + a3);
    }
}

// ---------------- per-(b,l) hop update: 256 threads for latency hiding -------
__global__ __launch_bounds__(256) void kh_rip(
    const float* __restrict__ E, const float* __restrict__ Wt,
    const int* __restrict__ mh, const int* __restrict__ mr, const int* __restrict__ mt,
    const int* __restrict__ seq, int hop, int last)
{
    __shared__ float sc[MM], pr[MM], u[DD], part[256], item_s[DD];
    const int bl = blockIdx.x, t = threadIdx.x;
    const int d = t & 63, quarter = t >> 6;
    const int mbase = (bl*NHOP + hop) * MM;

    if (t < DD)
        item_s[t] = hop ? g_item[bl*DD + t] : E[(long)seq[bl]*DD + t];

    // ---- issue score loads: 8 threads per m, 8 elems each ----
    const int m = t >> 3, e8 = t & 7;
    const int hid = mh[mbase + m], rid = mr[mbase + m];
    const float4* Vv = (const float4*)(g_V + ((long)bl*RR + rid) * DD) + e8*2;
    const float4* Hh = (const float4*)(E + (long)hid * DD) + e8*2;
    float4 va0 = Vv[0], va1 = Vv[1], ha0 = Hh[0], ha1 = Hh[1];

    // ---- prefetch t-rows: 8 per thread ----
    float treg[8];
    const int* mtb = mt + mbase + quarter*8;
    #pragma unroll
    for (int m2 = 0; m2 < 8; m2++)
        treg[m2] = E[(long)mtb[m2]*DD + d];

    // ---- score reduction (groups of 8 lanes) ----
    float acc = va0.x*ha0.x + va0.y*ha0.y + va0.z*ha0.z + va0.w*ha0.w
              + va1.x*ha1.x + va1.y*ha1.y + va1.z*ha1.z + va1.w*ha1.w;
    acc += __shfl_down_sync(0xffffffffu, acc, 4, 8);
    acc += __shfl_down_sync(0xffffffffu, acc, 2, 8);
    acc += __shfl_down_sync(0xffffffffu, acc, 1, 8);
    if (e8 == 0) sc[m] = acc;
    __syncthreads();

    // ---- softmax over 32 (warp 0) ----
    if (t < 32) {
        float v = sc[t];
        float mx = v;
        #pragma unroll
        for (int o = 16; o; o >>= 1) mx = fmaxf(mx, __shfl_xor_sync(0xffffffffu, mx, o));
        float e = __expf(v - mx);
        float s = e;
        #pragma unroll
        for (int o = 16; o; o >>= 1) s += __shfl_xor_sync(0xffffffffu, s, o);
        pr[t] = e / s;
    }
    __syncthreads();

    // ---- o[d] from prefetched registers (4-way split over m) ----
    float od = 0.f;
    #pragma unroll
    for (int m2 = 0; m2 < 8; m2++)
        od += pr[quarter*8 + m2] * treg[m2];
    part[t] = od;
    __syncthreads();
    if (t < DD) {
        float o = part[t] + part[t + 64] + part[t + 128] + part[t + 192];
        if (hop == 0) g_osum[bl*DD + t] = o;
        else          g_osum[bl*DD + t] += o;
        u[t] = o + item_s[t];
    }
    __syncthreads();

    if (!last) {
        const float4* wr = (const float4*)(Wt + d*DD) + quarter*4;
        const float4* uu = (const float4*)u + quarter*4;
        float a = 0.f;
        #pragma unroll
        for (int kk = 0; kk < 4; kk++) {
            float4 w = wr[kk], x = uu[kk];
            a += w.x*x.x + w.y*x.y + w.z*x.z + w.w*x.w;
        }
        part[t] = a;
        __syncthreads();
        if (t < DD)
            g_item[bl*DD + t] = lrelu(part[t] + part[t+64] + part[t+128] + part[t+192]);
    }
}

// ---------------- sequential interest scan (per batch b) ---------------------
__global__ __launch_bounds__(128) void ks_rip(
    const float* __restrict__ W1, const float* __restrict__ W2,
    const float* __restrict__ uemb, const int* __restrict__ user,
    const float* __restrict__ pemb, const float* __restrict__ E,
    const int* __restrict__ seq)
{
    __shared__ float S[LL*DD];
    __shared__ float AB[128];
    __shared__ float T[128];
    const int b = blockIdx.x, t = threadIdx.x;
    const int i = t & 63, path = t >> 6;

    const float* W = path ? W2 : W1;
    const float4* wr = (const float4*)(W + i*DD);
    float4 wv[16];
    #pragma unroll
    for (int kk = 0; kk < 16; kk++) wv[kk] = wr[kk];

    for (int idx = t; idx < LL*DD; idx += 128) {
        int l = idx >> 6, d = idx & 63;
        S[idx] = E[(long)seq[b*LL + l]*DD + d] + g_osum[b*LL*DD + idx];
    }

    float c = uemb[(long)user[b] * DD + i];
    __syncthreads();

    for (int st = 0; st < LL; st++) {
        float sv = S[st*DD + i];
        AB[path*64 + i] = path ? (sv * c) : (sv + c);
        __syncthreads();
        const float4* in = (const float4*)(AB + path*64);
        float a0 = 0.f, a1 = 0.f, a2 = 0.f, a3 = 0.f;
        #pragma unroll
        for (int kk = 0; kk < 16; kk += 4) {
            float4 x0 = in[kk],   x1 = in[kk+1], x2 = in[kk+2], x3 = in[kk+3];
            a0 += wv[kk  ].x*x0.x + wv[kk  ].y*x0.y + wv[kk  ].z*x0.z + wv[kk  ].w*x0.w;
            a1 += wv[kk+1].x*x1.x + wv[kk+1].y*x1.y + wv[kk+1].z*x1.z + wv[kk+1].w*x1.w;
            a2 += wv[kk+2].x*x2.x + wv[kk+2].y*x2.y + wv[kk+2].z*x2.z + wv[kk+2].w*x2.w;
            a3 += wv[kk+3].x*x3.x + wv[kk+3].y*x3.y + wv[kk+3].z*x3.z + wv[kk+3].w*x3.w;
        }
        float r = lrelu((a0 + a1) + (a2 + a3));
        T[path*64 + i] = r;
        __syncthreads();
        float out = T[i] + T[64 + i];
        c = out;
        if (path == 0)
            g_x[(b*LL + st)*DD + i] = out * 8.0f + pemb[st*DD + i];
    }
}

// ---------------- per-row LN -> Q, then q/k/v projections (block 0 only) -----
__global__ __launch_bounds__(128) void kq_rip(
    const float* __restrict__ lns, const float* __restrict__ lnb,
    const float* __restrict__ ipw, const float* __restrict__ ipb, int bb)
{
    __shared__ float xs[DD], Qs[DD];
    __shared__ float mv[2];
    const int bl = blockIdx.x, t = threadIdx.x;
    if (t < DD) xs[t] = g_x[bl*DD + t];
    __syncthreads();
    if (t < 32) {
        float s = xs[t] + xs[t + 32];
        #pragma unroll
        for (int o = 16; o; o >>= 1) s += __shfl_xor_sync(0xffffffffu, s, o);
        float mean = s * (1.f/64.f);
        float d0 = xs[t] - mean, d1 = xs[t+32] - mean;
        float vs = d0*d0 + d1*d1;
        #pragma unroll
        for (int o = 16; o; o >>= 1) vs += __shfl_xor_sync(0xffffffffu, vs, o);
        if (t == 0) { mv[0] = mean; mv[1] = rsqrtf(vs * (1.f/64.f) + 1e-8f); }
    }
    __syncthreads();
    if (t < DD) {
        float q = (xs[t] - mv[0]) * mv[1] * lns[bb*DD + t] + lnb[bb*DD + t];
        Qs[t] = q;
        g_Q[bl*DD + t] = q;
    }
    __syncthreads();

    for (int o = t; o < 3*DD; o += 128) {
        const float* src = (o < DD) ? Qs : xs;
        const float4* w4 = (const float4*)(ipw + ((long)bb*3*DD + o) * DD);
        const float4* s4 = (const float4*)src;
        float acc = 0.f;
        #pragma unroll
        for (int kk = 0; kk < 16; kk++) {
            float4 w = w4[kk], x = s4[kk];
            acc += w.x*x.x + w.y*x.y + w.z*x.z + w.w*x.w;
        }
        acc += ipb[bb*3*DD + o];
        if      (o < DD)   g_q[bl*DD + o      ] = acc;
        else if (o < 2*DD) g_k[bl*DD + o - 64 ] = acc;
        else               g_v[bl*DD + o - 128] = acc;
    }
}

// ---------------- causal attention, block = (b,h,qparity) --------------------
__global__ __launch_bounds__(256) void ka_rip()
{
    __shared__ float qh[LL*36], kh[LL*36], vh[LL*36];
    __shared__ float ps[8][52];
    const int blk = blockIdx.x;
    const int qs = blk & 1, h = (blk >> 1) & 1, b = blk >> 2;
    const int t = threadIdx.x;

    for (int idx = t; idx < LL*HDD; idx += 256) {
        int l = idx >> 5, d = idx & 31;
        int src = (b*LL + l)*DD + h*HDD + d;
        qh[l*36 + d] = g_q[src];
        kh[l*36 + d] = g_k[src];
        vh[l*36 + d] = g_v[src];
    }
    __syncthreads();

    const int w = t >> 5, lane = t & 31;
    const float scl = 0.17677669529663687f;
    for (int qi = 2*w + qs; qi < LL; qi += 16) {
        float4 qreg[8];
        const float4* qa = (const float4*)(qh + qi*36);
        #pragma unroll
        for (int kk = 0; kk < 8; kk++) qreg[kk] = qa[kk];

        int k0 = lane, k1 = lane + 32;
        float s0 = -3.0e38f, s1 = -3.0e38f;
        if (k0 <= qi) {
            const float4* ka = (const float4*)(kh + k0*36);
            float a = 0.f;
            #pragma unroll
            for (int kk = 0; kk < 8; kk++) {
                float4 kv = ka[kk];
                a += qreg[kk].x*kv.x + qreg[kk].y*kv.y + qreg[kk].z*kv.z + qreg[kk].w*kv.w;
            }
            s0 = a * scl;
        }
        if (k1 <= qi) {
            const float4* ka = (const float4*)(kh + k1*36);
            float a = 0.f;
            #pragma unroll
            for (int kk = 0; kk < 8; kk++) {
                float4 kv = ka[kk];
                a += qreg[kk].x*kv.x + qreg[kk].y*kv.y + qreg[kk].z*kv.z + qreg[kk].w*kv.w;
            }
            s1 = a * scl;
        }
        float mx = fmaxf(s0, s1);
        #pragma unroll
        for (int o = 16; o; o >>= 1) mx = fmaxf(mx, __shfl_xor_sync(0xffffffffu, mx, o));
        float e0 = (k0 <= qi) ? __expf(s0 - mx) : 0.f;
        float e1 = (k1 <= qi) ? __expf(s1 - mx) : 0.f;
        float sm = e0 + e1;
        #pragma unroll
        for (int o = 16; o; o >>= 1) sm += __shfl_xor_sync(0xffffffffu, sm, o);
        float inv = 1.f / sm;
        ps[w][k0] = e0 * inv;
        if (k1 < LL) ps[w][k1] = e1 * inv;
        __syncwarp();
        float acc = 0.f;
        for (int kj = 0; kj <= qi; kj++)
            acc += ps[w][kj] * vh[kj*36 + lane];
        g_ctx[(b*LL + qi)*DD + h*HDD + lane] = acc;
        __syncwarp();
    }
}

// ---------------- out-proj + residual + LN + FFN, then NEXT-block qkv or logits
__global__ __launch_bounds__(128) void km_rip(
    const float* __restrict__ opw, const float* __restrict__ opb,
    const float* __restrict__ fs,  const float* __restrict__ fb,
    const float* __restrict__ c1w, const float* __restrict__ c1b,
    const float* __restrict__ c2w, const float* __restrict__ c2b, int bb,
    int last, const float* __restrict__ E,
    const float* __restrict__ lls, const float* __restrict__ llb,
    const int* __restrict__ pos, const int* __restrict__ neg,
    float* __restrict__ out,
    const float* __restrict__ lns, const float* __restrict__ lnb,
    const float* __restrict__ ipw, const float* __restrict__ ipb)
{
    __shared__ float cs[DD], xr[DD], x2[DD], hdn[DD], part[128], Qs[DD];
    __shared__ float mv[2];
    const int bl = blockIdx.x, t = threadIdx.x;
    const int i = t & 63, half = t >> 6;
    if (t < DD) cs[t] = g_ctx[bl*DD + t];
    __syncthreads();

    {
        const float4* wr = (const float4*)(opw + ((long)bb*DD + i)*DD) + half*8;
        const float4* uu = (const float4*)cs + half*8;
        float a = 0.f;
        #pragma unroll
        for (int kk = 0; kk < 8; kk++) {
            float4 w = wr[kk], x = uu[kk];
            a += w.x*x.x + w.y*x.y + w.z*x.z + w.w*x.w;
        }
        part[t] = a;
    }
    __syncthreads();
    if (t < DD)
        xr[t] = part[t] + part[t+64] + opb[bb*DD + t] + g_Q[bl*DD + t];
    __syncthreads();

    if (t < 32) {
        float s = xr[t] + xr[t+32];
        #pragma unroll
        for (int o = 16; o; o >>= 1) s += __shfl_xor_sync(0xffffffffu, s, o);
        float mean = s * (1.f/64.f);
        float d0 = xr[t]-mean, d1 = xr[t+32]-mean;
        float vs = d0*d0 + d1*d1;
        #pragma unroll
        for (int o = 16; o; o >>= 1) vs += __shfl_xor_sync(0xffffffffu, vs, o);
        if (t == 0) { mv[0] = mean; mv[1] = rsqrtf(vs*(1.f/64.f) + 1e-8f); }
    }
    __syncthreads();
    if (t < DD)
        x2[t] = (xr[t] - mv[0]) * mv[1] * fs[bb*DD + t] + fb[bb*DD + t];
    __syncthreads();

    {
        const float4* wr = (const float4*)(c1w + ((long)bb*DD + i)*DD) + half*8;
        const float4* uu = (const float4*)x2 + half*8;
        float a = 0.f;
        #pragma unroll
        for (int kk = 0; kk < 8; kk++) {
            float4 w = wr[kk], x = uu[kk];
            a += w.x*x.x + w.y*x.y + w.z*x.z + w.w*x.w;
        }
        part[t] = a;
    }
    __syncthreads();
    if (t < DD) {
        float v = part[t] + part[t+64] + c1b[bb*DD + t];
        hdn[t] = v > 0.f ? v : 0.f;
    }
    __syncthreads();

    {
        const float4* wr = (const float4*)(c2w + ((long)bb*DD + i)*DD) + half*8;
        const float4* uu = (const float4*)hdn + half*8;
        float a = 0.f;
        #pragma unroll
        for (int kk = 0; kk < 8; kk++) {
            float4 w = wr[kk], x = uu[kk];
            a += w.x*x.x + w.y*x.y + w.z*x.z + w.w*x.w;
        }
        part[t] = a;
    }
    __syncthreads();
    // xr := new x (residual output of this transformer block)
    if (t < DD)
        xr[t] = x2[t] + part[t] + part[t+64] + c2b[bb*DD + t];
    __syncthreads();

    // LN stats on new x (both paths need it)
    if (t < 32) {
        float s = xr[t] + xr[t+32];
        #pragma unroll
        for (int o = 16; o; o >>= 1) s += __shfl_xor_sync(0xffffffffu, s, o);
        float mean = s * (1.f/64.f);
        float d0 = xr[t]-mean, d1 = xr[t+32]-mean;
        float vs = d0*d0 + d1*d1;
        #pragma unroll
        for (int o = 16; o; o >>= 1) vs += __shfl_xor_sync(0xffffffffu, vs, o);
        if (t == 0) { mv[0] = mean; mv[1] = rsqrtf(vs*(1.f/64.f) + 1e-8f); }
    }
    __syncthreads();

    if (!last) {
        // fused next-block LN + qkv (bb+1)
        const int b1 = bb + 1;
        if (t < DD) {
            float q = (xr[t] - mv[0]) * mv[1] * lns[b1*DD + t] + lnb[b1*DD + t];
            Qs[t] = q;
            g_Q[bl*DD + t] = q;
        }
        __syncthreads();
        for (int o = t; o < 3*DD; o += 128) {
            const float* src = (o < DD) ? Qs : xr;
            const float4* w4 = (const float4*)(ipw + ((long)b1*3*DD + o) * DD);
            const float4* s4 = (const float4*)src;
            float acc = 0.f;
            #pragma unroll
            for (int kk = 0; kk < 16; kk++) {
                float4 w = w4[kk], x = s4[kk];
                acc += w.x*x.x + w.y*x.y + w.z*x.z + w.w*x.w;
            }
            acc += ipb[b1*3*DD + o];
            if      (o < DD)   g_q[bl*DD + o      ] = acc;
            else if (o < 2*DD) g_k[bl*DD + o - 64 ] = acc;
            else               g_v[bl*DD + o - 128] = acc;
        }
        return;
    }

    // fused final LN + logits
    if (t < DD) {
        float lf = (xr[t] - mv[0]) * mv[1] * lls[t] + llb[t];
        part[t]      = lf * E[(long)pos[bl]*DD + t];
        part[t + 64] = lf * E[(long)neg[bl]*DD + t];
    }
    __syncthreads();
    if (t < 32) {
        float s = part[t] + part[t+32];
        #pragma unroll
        for (int o = 16; o; o >>= 1) s += __shfl_xor_sync(0xffffffffu, s, o);
        if (t == 0) out[bl] = s;
    } else if (t < 64) {
        int tn = t - 32;
        float s = part[64 + tn] + part[96 + tn];
        #pragma unroll
        for (int o = 16; o; o >>= 1) s += __shfl_xor_sync(0xffffffffu, s, o);
        if (tn == 0) out[BL + bl] = s;
    }
}

// ---------------- launch ------------------------------------------------------
extern "C" void kernel_launch(void* const* d_in, const int* in_sizes, int n_in,
                              void* d_out, int out_size)
{
    const float* uemb = (const float*)d_in[0];
    const float* E    = (const float*)d_in[1];
    const float* rel  = (const float*)d_in[2];
    const float* Wt   = (const float*)d_in[3];
    const float* W1   = (const float*)d_in[4];
    const float* W2   = (const float*)d_in[5];
    const float* pemb = (const float*)d_in[6];
    const float* lnas = (const float*)d_in[7];
    const float* lnab = (const float*)d_in[8];
    const float* ipw  = (const float*)d_in[9];
    const float* ipb  = (const float*)d_in[10];
    const float* opw  = (const float*)d_in[11];
    const float* opb  = (const float*)d_in[12];
    const float* fs   = (const float*)d_in[13];
    const float* fb   = (const float*)d_in[14];
    const float* c1w  = (const float*)d_in[15];
    const float* c1b  = (const float*)d_in[16];
    const float* c2w  = (const float*)d_in[17];
    const float* c2b  = (const float*)d_in[18];
    const float* lls  = (const float*)d_in[19];
    const float* llb  = (const float*)d_in[20];
    const int*   user = (const int*)d_in[21];
    const int*   seq  = (const int*)d_in[22];
    const int*   pos  = (const int*)d_in[23];
    const int*   neg  = (const int*)d_in[24];
    const int*   mh   = (const int*)d_in[25];
    const int*   mr   = (const int*)d_in[26];
    const int*   mt   = (const int*)d_in[27];
    float* out = (float*)d_out;

    for (int hop = 0; hop < NHOP; hop++) {
        kv_rip<<<320, 256>>>(rel, E, seq, hop);
        kh_rip<<<BL, 256>>>(E, Wt, mh, mr, mt, seq, hop, hop == NHOP - 1);
    }
    ks_rip<<<BB, 128>>>(W1, W2, uemb, user, pemb, E, seq);
    kq_rip<<<BL, 128>>>(lnas, lnab, ipw, ipb, 0);
    for (int bb = 0; bb < NBLK; bb++) {
        ka_rip<<<BB*HH*2, 256>>>();
        km_rip<<<BL, 128>>>(opw, opb, fs, fb, c1w, c1b, c2w, c2b, bb,
                            bb == NBLK - 1, E, lls, llb, pos, neg, out,
                            lnas, lnab, ipw, ipb);
    }
}